// round 1
// baseline (speedup 1.0000x reference)
#include <cuda_runtime.h>
#include <cstdint>
#include <cstddef>

// Problem constants
constexpr int Tn  = 2048;
constexpr int Cn  = 2048;
constexpr int Hh  = 32;
constexpr int Ssz = 64;
constexpr int HKV = 8;
constexpr size_t TC = (size_t)Tn * Cn;          // 4194304

// Scratch layout (single __device__ array; no allocations allowed)
constexpr size_t OFF_SX   = 0;
constexpr size_t OFF_XXX  = OFF_SX   + TC;
constexpr size_t OFF_MAA  = OFF_XXX  + TC;                // 5*2048
constexpr size_t OFF_MBUF = OFF_MAA  + 5 * 2048;          // T x 160
constexpr size_t OFF_XB   = OFF_MBUF + (size_t)Tn * 160;  // 5 x T x C
constexpr size_t OFF_R    = OFF_XB   + 5 * TC;
constexpr size_t OFF_K    = OFF_R    + TC;                // T x 512
constexpr size_t OFF_V    = OFF_K    + (size_t)Tn * 512;
constexpr size_t OFF_D1   = OFF_V    + (size_t)Tn * 512;  // T x 64
constexpr size_t OFF_EW   = OFF_D1   + (size_t)Tn * 64;
constexpr size_t OFF_KK   = OFF_EW   + TC;
constexpr size_t OFF_G    = OFF_KK   + TC;
constexpr size_t OFF_OS   = OFF_G    + TC;
constexpr size_t OFF_SF   = OFF_OS   + TC;                // 32*64*64
constexpr size_t SCRATCH_TOTAL = OFF_SF + (size_t)Hh * Ssz * Ssz;

__device__ float g_scratch[SCRATCH_TOTAL];

// ---------------------------------------------------------------------------
// prep: sx = (prev token | state0, zeroed at starts) - x ; xxx = x + sx*maa_x
// also packs the 5 per-branch maa vectors into one [5][C] buffer
// ---------------------------------------------------------------------------
__global__ void prep_kernel(const float* __restrict__ x,
                            const float* __restrict__ state,
                            const unsigned char* __restrict__ ns,
                            const float* __restrict__ tmx,
                            const float* __restrict__ tmr,
                            const float* __restrict__ tmk,
                            const float* __restrict__ tmv,
                            const float* __restrict__ tmw,
                            const float* __restrict__ tmg,
                            float* __restrict__ sx,
                            float* __restrict__ xxx,
                            float* __restrict__ maacat) {
    size_t idx = (size_t)blockIdx.x * blockDim.x + threadIdx.x;
    if (idx < TC) {
        int t = (int)(idx >> 11);
        int c = (int)(idx & 2047);
        float prev = (t == 0) ? state[c] : x[idx - Cn];
        if (ns[t]) prev = 0.0f;
        float xv = x[idx];
        float sxv = prev - xv;
        sx[idx] = sxv;
        xxx[idx] = xv + sxv * tmx[c];
    }
    if (idx < 5 * 2048) {
        int n = (int)(idx >> 11);
        int c = (int)(idx & 2047);
        const float* p = (n == 0) ? tmr : (n == 1) ? tmk : (n == 2) ? tmv
                       : (n == 3) ? tmw : tmg;
        maacat[idx] = p[c];
    }
}

// ---------------------------------------------------------------------------
// Generic fp32 GEMM: C = epi(A[M,K] @ B[K,N]); 128x128 tile, BK=8, 256 thr
// EPI: 0 plain | 1 tanh | 2 sigmoid | 3 token-shift-mix branch (grid.z = 5)
//      4 decay (-> ew & scaled k) | 5 plain with A-side elementwise gate
// ---------------------------------------------------------------------------
template <int EPI>
__global__ __launch_bounds__(256)
void gemm_k(const float* __restrict__ A, int lda,
            const float* __restrict__ B, int ldb,
            float* __restrict__ Cout, int ldc,
            int M, int N, int K,
            const float* __restrict__ bias,
            const float* __restrict__ amul,
            float* __restrict__ out2,
            const float* __restrict__ kin,
            const float* __restrict__ xp,
            const float* __restrict__ sxp,
            const float* __restrict__ maap) {
    if (EPI == 3) {
        // per-branch offsets: A cols z*32, B rows z*32 (w2 is [5][32][C] contiguous),
        // output buffer z*T*C, maa vector z*C
        A    += blockIdx.z * 32;
        B    += (size_t)blockIdx.z * 32 * 2048;
        Cout += (size_t)blockIdx.z * (size_t)M * (size_t)ldc;
        maap += (size_t)blockIdx.z * 2048;
    }

    __shared__ float As[8][128];
    __shared__ float Bs[8][128];

    int tid = threadIdx.x;
    int tx = tid & 15;   // N-direction
    int ty = tid >> 4;   // M-direction
    int bx = blockIdx.x;
    int by = blockIdx.y;

    float acc[8][8];
#pragma unroll
    for (int i = 0; i < 8; i++)
#pragma unroll
        for (int j = 0; j < 8; j++) acc[i][j] = 0.0f;

    int ar = tid >> 1;          // 0..127
    int ac = (tid & 1) * 4;     // 0 or 4
    int br = tid >> 5;          // 0..7
    int bc = (tid & 31) * 4;    // 0..124

    for (int k0 = 0; k0 < K; k0 += 8) {
        // load A tile (transposed into SMEM)
        {
            const float* ap = A + (size_t)(by * 128 + ar) * lda + k0 + ac;
            float4 av = *(const float4*)ap;
            if (EPI == 5) {
                float4 mv = *(const float4*)(amul + (size_t)(by * 128 + ar) * lda + k0 + ac);
                av.x *= mv.x; av.y *= mv.y; av.z *= mv.z; av.w *= mv.w;
            }
            As[ac + 0][ar] = av.x;
            As[ac + 1][ar] = av.y;
            As[ac + 2][ar] = av.z;
            As[ac + 3][ar] = av.w;
        }
        // load B tile (zero-pad past N)
        {
            int col = bx * 128 + bc;
            const float* bp = B + (size_t)(k0 + br) * ldb + col;
#pragma unroll
            for (int j = 0; j < 4; j++)
                Bs[br][bc + j] = (col + j < N) ? bp[j] : 0.0f;
        }
        __syncthreads();

#pragma unroll
        for (int kk = 0; kk < 8; kk++) {
            float a[8], b[8];
#pragma unroll
            for (int i = 0; i < 8; i++) a[i] = As[kk][ty * 8 + i];
#pragma unroll
            for (int j = 0; j < 8; j++) b[j] = Bs[kk][tx * 8 + j];
#pragma unroll
            for (int i = 0; i < 8; i++)
#pragma unroll
                for (int j = 0; j < 8; j++) acc[i][j] += a[i] * b[j];
        }
        __syncthreads();
    }

    int row0 = by * 128 + ty * 8;
    int col0 = bx * 128 + tx * 8;
#pragma unroll
    for (int i = 0; i < 8; i++) {
        int row = row0 + i;
#pragma unroll
        for (int j = 0; j < 8; j++) {
            int col = col0 + j;
            if (col >= N) continue;
            float v = acc[i][j];
            size_t oidx = (size_t)row * ldc + col;
            if (EPI == 0 || EPI == 5) {
                Cout[oidx] = v;
            } else if (EPI == 1) {
                Cout[oidx] = tanhf(v);
            } else if (EPI == 2) {
                Cout[oidx] = 1.0f / (1.0f + expf(-v));
            } else if (EPI == 3) {
                size_t idx = (size_t)row * 2048 + col;
                Cout[oidx] = xp[idx] + sxp[idx] * (maap[col] + v);
            } else if (EPI == 4) {
                float dec = v + bias[col];
                float lw = fmaxf(-expf(dec), -5.0f);
                float ew = expf(lw);
                Cout[oidx] = ew;  // exp(log_w)
                // k (grouped, H_KV=8) repeated 4x over heads, scaled by (1-ew)
                float kvv = kin[(size_t)row * 512 + (col >> 8) * 64 + (col & 63)];
                out2[oidx] = kvv * (1.0f - ew);
            }
        }
    }
}

// ---------------------------------------------------------------------------
// Sequential scan over T. Grid: (4 v-chunks, 32 heads), 256 threads.
// Thread (vl = tid/16, kg = tid%16) owns state s[k=kg*4..kg*4+3][v=vs+vl].
// ---------------------------------------------------------------------------
__global__ __launch_bounds__(256)
void scan_kernel(const float* __restrict__ r,
                 const float* __restrict__ kk,
                 const float* __restrict__ ew,
                 const float* __restrict__ v,
                 const unsigned char* __restrict__ ns,
                 const float* __restrict__ state,
                 float* __restrict__ out,
                 float* __restrict__ sfin) {
    int h = blockIdx.y;
    int vs = blockIdx.x * 16;
    int tid = threadIdx.x;
    int vl = tid >> 4;
    int kg = tid & 15;
    int vcol = vs + vl;
    int hv4 = (h >> 2) * 64;  // kv-head column base

    float s[4];
#pragma unroll
    for (int i = 0; i < 4; i++) {
        int krow = kg * 4 + i;
        s[i] = state[2048 + h * 4096 + krow * 64 + vcol];
    }

    __shared__ float rs[2][64], ks[2][64], ws[2][64], vsd[2][16];

    for (int t = 0; t < Tn; t++) {
        int b = t & 1;
        size_t base = (size_t)t * 2048 + h * 64;
        if (tid < 64)       rs[b][tid]        = r[base + tid];
        else if (tid < 128) ks[b][tid - 64]   = kk[base + (tid - 64)];
        else if (tid < 192) ws[b][tid - 128]  = ew[base + (tid - 128)];
        else if (tid < 208) vsd[b][tid - 192] = v[(size_t)t * 512 + hv4 + vs + (tid - 192)];
        __syncthreads();

        if (ns[t]) { s[0] = 0.f; s[1] = 0.f; s[2] = 0.f; s[3] = 0.f; }
        float vv = vsd[b][vl];
        float po = 0.0f;
#pragma unroll
        for (int i = 0; i < 4; i++) {
            int krow = kg * 4 + i;
            s[i] = s[i] * ws[b][krow] + ks[b][krow] * vv;
            po += rs[b][krow] * s[i];
        }
        po += __shfl_down_sync(0xffffffffu, po, 8, 16);
        po += __shfl_down_sync(0xffffffffu, po, 4, 16);
        po += __shfl_down_sync(0xffffffffu, po, 2, 16);
        po += __shfl_down_sync(0xffffffffu, po, 1, 16);
        if (kg == 0) out[base + vcol] = po;
    }

#pragma unroll
    for (int i = 0; i < 4; i++) {
        int krow = kg * 4 + i;
        sfin[h * 4096 + krow * 64 + vcol] = s[i];
    }
}

// ---------------------------------------------------------------------------
// tail: append new_state (row0 = x[length-1], rows 1..64 = final scan state)
// ---------------------------------------------------------------------------
__global__ void tail_kernel(const float* __restrict__ x,
                            const int* __restrict__ lenp,
                            const float* __restrict__ sfin,
                            float* __restrict__ out) {
    int idx = blockIdx.x * blockDim.x + threadIdx.x;
    if (idx >= 65 * 2048) return;
    int len = *lenp;
    float v;
    if (idx < 2048) v = x[(size_t)(len - 1) * 2048 + idx];
    else            v = sfin[idx - 2048];
    out[TC + idx] = v;
}

// ---------------------------------------------------------------------------
extern "C" void kernel_launch(void* const* d_in, const int* in_sizes, int n_in,
                              void* d_out, int out_size) {
    (void)in_sizes; (void)n_in;
    const float* x     = (const float*)d_in[0];
    const float* state = (const float*)d_in[1];
    const unsigned char* ns = (const unsigned char*)d_in[2];
    const int* lenp    = (const int*)d_in[3];
    const float* tmx   = (const float*)d_in[4];
    const float* tmr   = (const float*)d_in[5];
    const float* tmk   = (const float*)d_in[6];
    const float* tmv   = (const float*)d_in[7];
    const float* tmw   = (const float*)d_in[8];
    const float* tmg   = (const float*)d_in[9];
    const float* w1    = (const float*)d_in[10];  // [C, 160]
    const float* w2    = (const float*)d_in[11];  // [5, 32, C]
    const float* tdec  = (const float*)d_in[12];  // [C]
    const float* tdw1  = (const float*)d_in[13];  // [C, 64]
    const float* tdw2  = (const float*)d_in[14];  // [64, C]
    const float* Wq    = (const float*)d_in[15];
    const float* Wk    = (const float*)d_in[16];
    const float* Wv    = (const float*)d_in[17];
    const float* Wg    = (const float*)d_in[18];
    const float* Wo    = (const float*)d_in[19];
    float* out = (float*)d_out;

    float* S = nullptr;
    cudaGetSymbolAddress((void**)&S, g_scratch);

    float* sx    = S + OFF_SX;
    float* xxx   = S + OFF_XXX;
    float* maa   = S + OFF_MAA;
    float* mbuf  = S + OFF_MBUF;
    float* xb    = S + OFF_XB;
    float* rbuf  = S + OFF_R;
    float* kraw  = S + OFF_K;
    float* vbuf  = S + OFF_V;
    float* d1    = S + OFF_D1;
    float* ewb   = S + OFF_EW;
    float* kkb   = S + OFF_KK;
    float* gbuf  = S + OFF_G;
    float* oscan = S + OFF_OS;
    float* sfin  = S + OFF_SF;

    // 1. token shift + maa pack
    prep_kernel<<<(unsigned)((TC + 255) / 256), 256>>>(
        x, state, ns, tmx, tmr, tmk, tmv, tmw, tmg, sx, xxx, maa);

    // 2. m = tanh(xxx @ w1)   [T,160]
    gemm_k<1><<<dim3(2, 16), 256>>>(xxx, 2048, w1, 160, mbuf, 160,
                                    Tn, 160, 2048,
                                    nullptr, nullptr, nullptr, nullptr,
                                    nullptr, nullptr, nullptr);

    // 3. 5 branches: xb[z] = x + sx*(maa_z + m_z @ w2_z)   [5,T,C]
    gemm_k<3><<<dim3(16, 16, 5), 256>>>(mbuf, 160, w2, 2048, xb, 2048,
                                        Tn, 2048, 32,
                                        nullptr, nullptr, nullptr, nullptr,
                                        x, sx, maa);

    // 4. r = xr @ Wq   [T,2048]
    gemm_k<0><<<dim3(16, 16), 256>>>(xb + 0 * TC, 2048, Wq, 2048, rbuf, 2048,
                                     Tn, 2048, 2048,
                                     nullptr, nullptr, nullptr, nullptr,
                                     nullptr, nullptr, nullptr);
    // 5. k = xk @ Wk   [T,512]
    gemm_k<0><<<dim3(4, 16), 256>>>(xb + 1 * TC, 2048, Wk, 512, kraw, 512,
                                    Tn, 512, 2048,
                                    nullptr, nullptr, nullptr, nullptr,
                                    nullptr, nullptr, nullptr);
    // 6. v = xv @ Wv   [T,512]
    gemm_k<0><<<dim3(4, 16), 256>>>(xb + 2 * TC, 2048, Wv, 512, vbuf, 512,
                                    Tn, 512, 2048,
                                    nullptr, nullptr, nullptr, nullptr,
                                    nullptr, nullptr, nullptr);
    // 7. d1 = tanh(xw @ tdw1)   [T,64]
    gemm_k<1><<<dim3(1, 16), 256>>>(xb + 3 * TC, 2048, tdw1, 64, d1, 64,
                                    Tn, 64, 2048,
                                    nullptr, nullptr, nullptr, nullptr,
                                    nullptr, nullptr, nullptr);
    // 8. dec = d1 @ tdw2 + time_decay -> ew = exp(log_w), kk = k_rep*(1-ew)
    gemm_k<4><<<dim3(16, 16), 256>>>(d1, 64, tdw2, 2048, ewb, 2048,
                                     Tn, 2048, 64,
                                     tdec, nullptr, kkb, kraw,
                                     nullptr, nullptr, nullptr);
    // 9. g = sigmoid(xg @ Wg)   [T,2048]
    gemm_k<2><<<dim3(16, 16), 256>>>(xb + 4 * TC, 2048, Wg, 2048, gbuf, 2048,
                                     Tn, 2048, 2048,
                                     nullptr, nullptr, nullptr, nullptr,
                                     nullptr, nullptr, nullptr);

    // 10. sequential scan
    scan_kernel<<<dim3(4, 32), 256>>>(rbuf, kkb, ewb, vbuf, ns, state,
                                      oscan, sfin);

    // 11. out = (oscan * g) @ Wo
    gemm_k<5><<<dim3(16, 16), 256>>>(oscan, 2048, Wo, 2048, out, 2048,
                                     Tn, 2048, 2048,
                                     nullptr, gbuf, nullptr, nullptr,
                                     nullptr, nullptr, nullptr);

    // 12. new_state, if the output buffer includes it
    if ((size_t)out_size >= TC + 65 * 2048) {
        tail_kernel<<<(65 * 2048 + 255) / 256, 256>>>(x, lenp, sfin, out);
    }
}